// round 9
// baseline (speedup 1.0000x reference)
#include <cuda_runtime.h>
#include <stdint.h>

#define Bc 32
#define Sc 128
#define Hc 128
#define BSH (Bc * Sc * Hc)

__device__ float g_M[BSH];
// duplicated W1: Wd[scale][j][s][t] = (W1, W1) as ull  (2*128*128*128*8 B = 33.5 MB)
__device__ __align__(16) unsigned long long g_Wd[2 * 128 * 128 * 128];

// ---------------------------------------------------------------------------
__device__ __forceinline__ float gelu_f(float x) {
    return 0.5f * x * (1.0f + erff(x * 0.7071067811865476f));
}
__device__ __forceinline__ unsigned long long dup2(float x) {
    unsigned long long r; unsigned int u = __float_as_uint(x);
    asm("mov.b64 %0, {%1, %1};" : "=l"(r) : "r"(u)); return r;
}
__device__ __forceinline__ void fma2(unsigned long long &d, unsigned long long a,
                                     unsigned long long b) {
    asm("fma.rn.f32x2 %0, %1, %2, %3;" : "=l"(d) : "l"(a), "l"(b), "l"(d));
}
__device__ __forceinline__ float lo32(unsigned long long v) {
    return __uint_as_float((unsigned int)v);
}
__device__ __forceinline__ float hi32(unsigned long long v) {
    return __uint_as_float((unsigned int)(v >> 32));
}
__device__ __forceinline__ uint32_t s2u(const void* p) {
    uint32_t a;
    asm("{ .reg .u64 t; cvta.to.shared.u64 t, %1; cvt.u32.u64 %0, t; }" : "=r"(a) : "l"(p));
    return a;
}
__device__ __forceinline__ void cpasync16(uint32_t dst, const void* src) {
    asm volatile("cp.async.ca.shared.global [%0], [%1], 16;" :: "r"(dst), "l"(src));
}
#define CP_COMMIT() asm volatile("cp.async.commit_group;" ::: "memory")
#define CP_WAIT0()  asm volatile("cp.async.wait_group 0;" ::: "memory")
#define CP_WAIT1()  asm volatile("cp.async.wait_group 1;" ::: "memory")

// ---------------------------------------------------------------------------
// prep: duplicate W1 floats into (v,v) ulonglong pairs
// ---------------------------------------------------------------------------
__global__ void prep_kernel(const float* __restrict__ W1,
                            unsigned long long* __restrict__ Wd)
{
    int i = (blockIdx.x * blockDim.x + threadIdx.x) * 4;   // 4 floats/thread
    float4 v = *(const float4*)(W1 + i);
    ulonglong2 a, b;
    a.x = dup2(v.x); a.y = dup2(v.y);
    b.x = dup2(v.z); b.y = dup2(v.w);
    *(ulonglong2*)(Wd + i)     = a;
    *(ulonglong2*)(Wd + i + 2) = b;
}

// ---------------------------------------------------------------------------
// Mix kernel v3: class-batched, 3 CTAs/SM, zero-MOV FFMA2 inner loop.
// Class s = ceil((j+1)/16): 16 j's, 2s t-slabs (8 cols) per j -> 4s CTAs.
// Warp w: slab_id = blk*8+w; j = 16(s-1) + slab_id/(2s); t0 = (slab_id%(2s))*8.
// Thread (lane): hg = lane>>1 (8 h's, packed pairs), tg = lane&1 (4 t's).
//   Y[h,t] = sum_k X[b,k,h] * W1[j,k,t]; out += gelu(Y+b1)*W2 (atomicAdd)
// ---------------------------------------------------------------------------
__global__ __launch_bounds__(256, 3) void mix_kernel(
    const float* __restrict__ X,                    // [B,S,H]
    const unsigned long long* __restrict__ Wd,      // dup W1, this scale
    const float* __restrict__ b1,                   // [S,S]
    const float* __restrict__ W2,                   // [S,S]
    float* __restrict__ out)                        // pre-init base + b2
{
    __shared__ __align__(16) float Xs[2][16][128];                  // 16 KB
    __shared__ __align__(16) unsigned long long Wds[2][16][8][8];   // 16 KB

    const int bx = blockIdx.x;
    const int b  = bx & 31;
    const int cb = bx >> 5;          // 0..143, descending s
    int s, cbase;
    if      (cb < 32)  { s = 8; cbase = 0;   }
    else if (cb < 60)  { s = 7; cbase = 32;  }
    else if (cb < 84)  { s = 6; cbase = 60;  }
    else if (cb < 104) { s = 5; cbase = 84;  }
    else if (cb < 120) { s = 4; cbase = 104; }
    else if (cb < 132) { s = 3; cbase = 120; }
    else if (cb < 140) { s = 2; cbase = 132; }
    else               { s = 1; cbase = 140; }
    const int blk = cb - cbase;      // [0, 4s)

    const int tid  = threadIdx.x;
    const int w    = tid >> 5;
    const int lane = tid & 31;
    const int hg   = lane >> 1;      // 16 h-groups of 8
    const int tg   = lane & 1;       // 2 t-groups of 4
    const int h0   = hg * 8;

    const int slab_id = blk * 8 + w;
    const int jloc    = slab_id / (2 * s);
    const int tsl     = slab_id - jloc * (2 * s);
    const int j       = ((s - 1) << 4) + jloc;
    const int t0      = tsl * 8;

    const float* Xg = X + (long)b * Sc * Hc;
    const uint32_t xsb = s2u(Xs), wsb = s2u(Wds);

    unsigned long long acc[4][4];    // [h-pair][t]
#pragma unroll
    for (int r = 0; r < 4; ++r)
#pragma unroll
        for (int c = 0; c < 4; ++c) acc[r][c] = 0ull;

    // ---- chunk issue: X 8KB + dup-W 8KB ----
    auto issue = [&](int c, int buf) {
        const int k0 = c << 4;
#pragma unroll
        for (int p = 0; p < 2; ++p) {   // X: 512 x 16B
            int i = tid + p * 256;
            int row = i >> 5, c4 = (i & 31) * 4;
            cpasync16(xsb + (uint32_t)(buf * 2048 + row * 128 + c4) * 4,
                      Xg + (k0 + row) * 128 + c4);
        }
#pragma unroll
        for (int p = 0; p < 2; ++p) {   // W: 512 x 16B (2 ull each)
            int i = tid + p * 256;
            int kk = i >> 5, rem = i & 31;
            int lw = rem >> 2, o4 = rem & 3;
            int sid = blk * 8 + lw;
            int jl = sid / (2 * s);
            int jj = ((s - 1) << 4) + jl;
            int tt = (sid - jl * 2 * s) * 8;
            cpasync16(wsb + (uint32_t)(((buf * 16 + kk) * 8 + lw) * 8 + o4 * 2) * 8,
                      Wd + ((long)jj * 128 + k0 + kk) * 128 + tt + o4 * 2);
        }
    };

    issue(0, 0);
    CP_COMMIT();
    if (s > 1) { issue(1, 1); CP_COMMIT(); }

    for (int c = 0; c < s; ++c) {
        if (c == s - 1) { CP_WAIT0(); } else { CP_WAIT1(); }
        __syncthreads();
        const int buf = c & 1;
#pragma unroll
        for (int kk = 0; kk < 16; ++kk) {
            ulonglong2 xa = *(const ulonglong2*)&Xs[buf][kk][h0];
            ulonglong2 xb = *(const ulonglong2*)&Xs[buf][kk][h0 + 4];
            ulonglong2 wa = *(const ulonglong2*)&Wds[buf][kk][w][tg * 4];
            ulonglong2 wb = *(const ulonglong2*)&Wds[buf][kk][w][tg * 4 + 2];
            fma2(acc[0][0], xa.x, wa.x); fma2(acc[0][1], xa.x, wa.y);
            fma2(acc[0][2], xa.x, wb.x); fma2(acc[0][3], xa.x, wb.y);
            fma2(acc[1][0], xa.y, wa.x); fma2(acc[1][1], xa.y, wa.y);
            fma2(acc[1][2], xa.y, wb.x); fma2(acc[1][3], xa.y, wb.y);
            fma2(acc[2][0], xb.x, wa.x); fma2(acc[2][1], xb.x, wa.y);
            fma2(acc[2][2], xb.x, wb.x); fma2(acc[2][3], xb.x, wb.y);
            fma2(acc[3][0], xb.y, wa.x); fma2(acc[3][1], xb.y, wa.y);
            fma2(acc[3][2], xb.y, wb.x); fma2(acc[3][3], xb.y, wb.y);
        }
        __syncthreads();
        if (c + 2 < s) { issue(c + 2, buf); }
        CP_COMMIT();
    }

    // ---- epilogue: gelu * W2, reduce over t (4 local + shfl over tg) ----
    float part[8];
#pragma unroll
    for (int r = 0; r < 8; ++r) part[r] = 0.0f;
#pragma unroll
    for (int c = 0; c < 4; ++c) {
        int t = t0 + tg * 4 + c;
        float b1v = b1[j * Sc + t];   // zero for t > j
        float w2v = W2[j * Sc + t];   // zero for t > j
#pragma unroll
        for (int r = 0; r < 4; ++r) {
            unsigned long long v = acc[r][c];
            part[2 * r]     += gelu_f(lo32(v) + b1v) * w2v;
            part[2 * r + 1] += gelu_f(hi32(v) + b1v) * w2v;
        }
    }
#pragma unroll
    for (int r = 0; r < 8; ++r)
        part[r] += __shfl_xor_sync(0xffffffffu, part[r], 1);
    if (tg == 0) {
        float* o = out + ((long)b * Sc + j) * Hc + h0;
#pragma unroll
        for (int r = 0; r < 8; ++r) atomicAdd(o + r, part[r]);
    }
}

// ---------------------------------------------------------------------------
// init: out[b,j,h] = base[b,j,h] + b2[j]
// ---------------------------------------------------------------------------
__global__ void init_kernel(const float4* __restrict__ base,
                            const float* __restrict__ b2,
                            float4* __restrict__ out)
{
    int i = blockIdx.x * blockDim.x + threadIdx.x;
    if (i < BSH / 4) {
        int j = (i >> 5) & 127;
        float bv = b2[j];
        float4 v = base[i];
        v.x += bv; v.y += bv; v.z += bv; v.w += bv;
        out[i] = v;
    }
}

// ---------------------------------------------------------------------------
// Fused MLP: out = gelu(in @ Wm1 + bm1) @ Wm2 + bm2   (row stride 132)
// ---------------------------------------------------------------------------
#define MRS 132
#define MLP_SMEM_BYTES ((2 * 32 * MRS + 2 * 128 * 128) * 4)

__global__ __launch_bounds__(256, 1) void mlp_fused(
    const float* __restrict__ in, const float* __restrict__ Wm1,
    const float* __restrict__ bm1, const float* __restrict__ Wm2,
    const float* __restrict__ bm2, float* __restrict__ out)
{
    extern __shared__ __align__(16) float sm[];
    float* A    = sm;
    float* Mid  = sm + 32 * MRS;
    float* W1s  = sm + 2 * 32 * MRS;
    float* W2s  = W1s + 128 * 128;

    const int tid = threadIdx.x;
    const int r   = tid >> 3;
    const int cg  = tid & 7;
    const int c0  = cg * 16;
    const int r0g = blockIdx.x * 32;
    const uint32_t smb = s2u(sm);

    for (int i = tid; i < 32 * 32; i += 256) {
        int row = i >> 5, c4 = (i & 31) * 4;
        cpasync16(smb + (uint32_t)(row * MRS + c4) * 4,
                  in + (r0g + row) * 128 + c4);
    }
    for (int i = tid; i < 128 * 32; i += 256) {
        int row = i >> 5, c4 = (i & 31) * 4;
        cpasync16(smb + (uint32_t)(2 * 32 * MRS + row * 128 + c4) * 4,
                  Wm1 + row * 128 + c4);
    }
    CP_COMMIT();
    for (int i = tid; i < 128 * 32; i += 256) {
        int row = i >> 5, c4 = (i & 31) * 4;
        cpasync16(smb + (uint32_t)(2 * 32 * MRS + 128 * 128 + row * 128 + c4) * 4,
                  Wm2 + row * 128 + c4);
    }
    CP_COMMIT();

    CP_WAIT1();
    __syncthreads();

    unsigned long long acc[8];
#pragma unroll
    for (int c = 0; c < 8; ++c) acc[c] = 0ull;
    {
        const float* Ar = A + r * MRS;
        for (int k = 0; k < 128; ++k) {
            unsigned long long ad = dup2(Ar[k]);
            const ulonglong2* wr = (const ulonglong2*)&W1s[k * 128 + c0];
            ulonglong2 w0 = wr[0], w1 = wr[1], w2 = wr[2], w3 = wr[3];
            fma2(acc[0], ad, w0.x); fma2(acc[1], ad, w0.y);
            fma2(acc[2], ad, w1.x); fma2(acc[3], ad, w1.y);
            fma2(acc[4], ad, w2.x); fma2(acc[5], ad, w2.y);
            fma2(acc[6], ad, w3.x); fma2(acc[7], ad, w3.y);
        }
        float* Mr = Mid + r * MRS + c0;
#pragma unroll
        for (int c = 0; c < 16; ++c) {
            unsigned long long v = acc[c >> 1];
            float y = ((c & 1) ? hi32(v) : lo32(v)) + bm1[c0 + c];
            Mr[c] = gelu_f(y);
        }
    }
    CP_WAIT0();
    __syncthreads();

#pragma unroll
    for (int c = 0; c < 8; ++c) acc[c] = 0ull;
    {
        const float* Mr = Mid + r * MRS;
        for (int k = 0; k < 128; ++k) {
            unsigned long long ad = dup2(Mr[k]);
            const ulonglong2* wr = (const ulonglong2*)&W2s[k * 128 + c0];
            ulonglong2 w0 = wr[0], w1 = wr[1], w2 = wr[2], w3 = wr[3];
            fma2(acc[0], ad, w0.x); fma2(acc[1], ad, w0.y);
            fma2(acc[2], ad, w1.x); fma2(acc[3], ad, w1.y);
            fma2(acc[4], ad, w2.x); fma2(acc[5], ad, w2.y);
            fma2(acc[6], ad, w3.x); fma2(acc[7], ad, w3.y);
        }
        float o[16];
#pragma unroll
        for (int c = 0; c < 16; ++c) {
            unsigned long long v = acc[c >> 1];
            o[c] = ((c & 1) ? hi32(v) : lo32(v)) + bm2[c0 + c];
        }
        float* og = out + (r0g + r) * 128 + c0;
        *(float4*)&og[0]  = make_float4(o[0], o[1], o[2], o[3]);
        *(float4*)&og[4]  = make_float4(o[4], o[5], o[6], o[7]);
        *(float4*)&og[8]  = make_float4(o[8], o[9], o[10], o[11]);
        *(float4*)&og[12] = make_float4(o[12], o[13], o[14], o[15]);
    }
}

// ---------------------------------------------------------------------------
__global__ void copy_kernel(const float4* __restrict__ src,
                            float4* __restrict__ dst, int n4)
{
    int i = blockIdx.x * blockDim.x + threadIdx.x;
    if (i < n4) dst[i] = src[i];
}

// ---------------------------------------------------------------------------
extern "C" void kernel_launch(void* const* d_in, const int* in_sizes, int n_in,
                              void* d_out, int out_size)
{
    const float* trend0 = (const float*)d_in[0];
    const float* trend1 = (const float*)d_in[1];
    const float* trend2 = (const float*)d_in[2];
    const float* W1     = (const float*)d_in[3];
    const float* b1     = (const float*)d_in[4];
    const float* W2     = (const float*)d_in[5];
    const float* b2     = (const float*)d_in[6];
    const float* Wm1    = (const float*)d_in[7];
    const float* bm1    = (const float*)d_in[8];
    const float* Wm2    = (const float*)d_in[9];
    const float* bm2    = (const float*)d_in[10];

    float* out = (float*)d_out;
    float* O0 = out;
    float* O1 = out + BSH;
    float* O2 = out + 2 * BSH;

    float* pM;
    unsigned long long* pWd;
    cudaGetSymbolAddress((void**)&pM, g_M);
    cudaGetSymbolAddress((void**)&pWd, g_Wd);

    cudaFuncSetAttribute(mlp_fused, cudaFuncAttributeMaxDynamicSharedMemorySize,
                         MLP_SMEM_BYTES);

    dim3 blk(256);
    dim3 mixGrid(144 * Bc);      // 4608 blocks, descending class size
    dim3 initGrid(BSH / 4 / 256);

    // duplicate W1 (both scales)
    prep_kernel<<<2 * 128 * 16384 / 4 / 256, blk>>>(W1, pWd);

    // scale i=0: X = trend2, base = trend1 -> O1 = mlp(M0)
    init_kernel<<<initGrid, blk>>>((const float4*)trend1, b2, (float4*)pM);
    mix_kernel<<<mixGrid, blk>>>(trend2, pWd, b1, W2, pM);
    mlp_fused<<<128, blk, MLP_SMEM_BYTES>>>(pM, Wm1, bm1, Wm2, bm2, O1);

    // scale i=1: X = O1, base = trend0 -> O0 = mlp(M1)
    init_kernel<<<initGrid, blk>>>((const float4*)trend0, b2 + Sc, (float4*)pM);
    mix_kernel<<<mixGrid, blk>>>(O1, pWd + (long)128 * 128 * 128,
                                 b1 + Sc * Sc, W2 + Sc * Sc, pM);
    mlp_fused<<<128, blk, MLP_SMEM_BYTES>>>(pM, Wm1, bm1, Wm2, bm2, O0);

    // out2 = trend2
    copy_kernel<<<BSH / 4 / 256, 256>>>((const float4*)trend2, (float4*)O2,
                                        BSH / 4);
}

// round 10
// speedup vs baseline: 1.4682x; 1.4682x over previous
#include <cuda_runtime.h>
#include <stdint.h>

#define Bc 32
#define Sc 128
#define Hc 128
#define BSH (Bc * Sc * Hc)

__device__ float g_M[BSH];

// ---------------------------------------------------------------------------
__device__ __forceinline__ float gelu_f(float x) {
    return 0.5f * x * (1.0f + erff(x * 0.7071067811865476f));
}
__device__ __forceinline__ unsigned long long dup2(float x) {
    unsigned long long r; unsigned int u = __float_as_uint(x);
    asm("mov.b64 %0, {%1, %1};" : "=l"(r) : "r"(u)); return r;
}
__device__ __forceinline__ void fma2(unsigned long long &d, unsigned long long a,
                                     unsigned long long b) {
    asm("fma.rn.f32x2 %0, %1, %2, %3;" : "=l"(d) : "l"(a), "l"(b), "l"(d));
}
__device__ __forceinline__ float lo32(unsigned long long v) {
    return __uint_as_float((unsigned int)v);
}
__device__ __forceinline__ float hi32(unsigned long long v) {
    return __uint_as_float((unsigned int)(v >> 32));
}
__device__ __forceinline__ uint32_t s2u(const void* p) {
    uint32_t a;
    asm("{ .reg .u64 t; cvta.to.shared.u64 t, %1; cvt.u32.u64 %0, t; }" : "=r"(a) : "l"(p));
    return a;
}
__device__ __forceinline__ void cpasync16(uint32_t dst, const void* src) {
    asm volatile("cp.async.ca.shared.global [%0], [%1], 16;" :: "r"(dst), "l"(src));
}
#define CP_COMMIT() asm volatile("cp.async.commit_group;" ::: "memory")
#define CP_WAIT0()  asm volatile("cp.async.wait_group 0;" ::: "memory")
#define CP_WAIT1()  asm volatile("cp.async.wait_group 1;" ::: "memory")

// ---------------------------------------------------------------------------
// Mix kernel (R8 version — best measured): class-batched uniform blocks.
// Class s = ceil((j+1)/16): j in [16(s-1), 16s-1], K16 = 16s.
// Per class: 16 j's x s slabs = 16s warp-slabs -> 2s blocks of 8 warps.
// ---------------------------------------------------------------------------
__global__ __launch_bounds__(256, 2) void mix_kernel(
    const float* __restrict__ X,     // [B,S,H]
    const float* __restrict__ W1,    // [S,S,S] (this scale)
    const float* __restrict__ b1,    // [S,S]
    const float* __restrict__ W2,    // [S,S]
    float* __restrict__ out)         // [B,S,H], pre-initialized
{
    __shared__ __align__(16) float Xs[2][16][128];
    __shared__ __align__(16) float Ws[2][16][128];   // cols = 8 warps x 16 t

    const int bx = blockIdx.x;
    const int b  = bx & 31;
    const int cb = bx >> 5;          // 0..71, descending s
    int s, cbase;
    if      (cb < 16) { s = 8; cbase = 0;  }
    else if (cb < 30) { s = 7; cbase = 16; }
    else if (cb < 42) { s = 6; cbase = 30; }
    else if (cb < 52) { s = 5; cbase = 42; }
    else if (cb < 60) { s = 4; cbase = 52; }
    else if (cb < 66) { s = 3; cbase = 60; }
    else if (cb < 70) { s = 2; cbase = 66; }
    else              { s = 1; cbase = 70; }
    const int blk8 = cb - cbase;     // [0, 2s)

    const int tid  = threadIdx.x;
    const int w    = tid >> 5;
    const int lane = tid & 31;
    const int hg   = lane >> 1;      // h-group: 8 rows
    const int tg   = lane & 1;       // t-group: 8 cols
    const int h0   = hg * 8;

    const int slab_id = blk8 * 8 + w;
    const int jloc    = slab_id / s;
    const int slabl   = slab_id - jloc * s;
    const int j       = ((s - 1) << 4) + jloc;
    const int t0      = slabl << 4;

    const float* Xg = X + (long)b * Sc * Hc;
    const uint32_t xsb = s2u(Xs), wsb = s2u(Ws);

    unsigned long long acc[8][4];
#pragma unroll
    for (int r = 0; r < 8; ++r)
#pragma unroll
        for (int c = 0; c < 4; ++c) acc[r][c] = 0ull;

    auto issue = [&](int c, int buf) {
        const int k0 = c << 4;
#pragma unroll
        for (int p = 0; p < 2; ++p) {  // X: 512 float4
            int i = tid + p * 256;
            int row = i >> 5, c4 = (i & 31) * 4;
            cpasync16(xsb + (uint32_t)(buf * 2048 + row * 128 + c4) * 4,
                      Xg + (k0 + row) * 128 + c4);
        }
#pragma unroll
        for (int p = 0; p < 2; ++p) {  // W: 512 float4 (gathered per warp slab)
            int i = tid + p * 256;
            int row = i >> 5, cc = i & 31;
            int lw = cc >> 2, c4 = (cc & 3) * 4;
            int sid = blk8 * 8 + lw;
            int jl = sid / s;
            int jj = ((s - 1) << 4) + jl;
            int tt = (sid - jl * s) << 4;
            cpasync16(wsb + (uint32_t)(buf * 2048 + row * 128 + lw * 16 + c4) * 4,
                      W1 + (long)jj * 16384 + (k0 + row) * 128 + tt + c4);
        }
    };

    issue(0, 0);
    CP_COMMIT();
    if (s > 1) { issue(1, 1); CP_COMMIT(); }

    const int tl = w * 16 + tg * 8;
    for (int c = 0; c < s; ++c) {
        if (c == s - 1) { CP_WAIT0(); } else { CP_WAIT1(); }
        __syncthreads();
        const int buf = c & 1;
#pragma unroll
        for (int kk = 0; kk < 16; ++kk) {
            float4 x0 = *(const float4*)&Xs[buf][kk][h0];
            float4 x1 = *(const float4*)&Xs[buf][kk][h0 + 4];
            ulonglong2 w0 = *(const ulonglong2*)&Ws[buf][kk][tl];
            ulonglong2 w1 = *(const ulonglong2*)&Ws[buf][kk][tl + 4];
            float xv[8] = {x0.x, x0.y, x0.z, x0.w, x1.x, x1.y, x1.z, x1.w};
#pragma unroll
            for (int r = 0; r < 8; ++r) {
                unsigned long long ad = dup2(xv[r]);
                fma2(acc[r][0], ad, w0.x);
                fma2(acc[r][1], ad, w0.y);
                fma2(acc[r][2], ad, w1.x);
                fma2(acc[r][3], ad, w1.y);
            }
        }
        __syncthreads();
        if (c + 2 < s) { issue(c + 2, buf); }
        CP_COMMIT();
    }

    // epilogue: gelu * W2, reduce over t, atomicAdd into out
    float part[8];
#pragma unroll
    for (int r = 0; r < 8; ++r) part[r] = 0.0f;
    const int tbase = t0 + tg * 8;
#pragma unroll
    for (int c = 0; c < 8; ++c) {
        int t = tbase + c;
        float b1v = b1[j * Sc + t];   // zero for t > j
        float w2v = W2[j * Sc + t];   // zero for t > j
#pragma unroll
        for (int r = 0; r < 8; ++r) {
            unsigned long long v = acc[r][c >> 1];
            float y = ((c & 1) ? hi32(v) : lo32(v)) + b1v;
            part[r] += gelu_f(y) * w2v;
        }
    }
#pragma unroll
    for (int r = 0; r < 8; ++r)
        part[r] += __shfl_xor_sync(0xffffffffu, part[r], 1);
    if (tg == 0) {
        float* o = out + ((long)b * Sc + j) * Hc + h0;
#pragma unroll
        for (int r = 0; r < 8; ++r) atomicAdd(o + r, part[r]);
    }
}

// ---------------------------------------------------------------------------
// init: out[b,j,h] = base[b,j,h] + b2[j]
// ---------------------------------------------------------------------------
__global__ void init_kernel(const float4* __restrict__ base,
                            const float* __restrict__ b2,
                            float4* __restrict__ out)
{
    int i = blockIdx.x * blockDim.x + threadIdx.x;
    if (i < BSH / 4) {
        int j = (i >> 5) & 127;
        float bv = b2[j];
        float4 v = base[i];
        v.x += bv; v.y += bv; v.z += bv; v.w += bv;
        out[i] = v;
    }
}

// ---------------------------------------------------------------------------
// Fused MLP v2: out = gelu(in @ Wm1 + bm1) @ Wm2 + bm2
// 128 blocks x 512 threads x 32 rows. Thread = 1 row x 8 cols.
// Both k-loops unrolled (batched LDS + ILP); 16 warps/SM for latency cover.
// ---------------------------------------------------------------------------
#define MRS 132
#define MLP_SMEM_BYTES ((2 * 32 * MRS + 2 * 128 * 128) * 4)

__global__ __launch_bounds__(512, 1) void mlp_fused(
    const float* __restrict__ in,    // [4096,128]
    const float* __restrict__ Wm1,   // [128,128]
    const float* __restrict__ bm1,   // [128]
    const float* __restrict__ Wm2,   // [128,128]
    const float* __restrict__ bm2,   // [128]
    float* __restrict__ out)         // [4096,128]
{
    extern __shared__ __align__(16) float sm[];
    float* A    = sm;                  // [32][MRS]
    float* Mid  = sm + 32 * MRS;       // [32][MRS]
    float* W1s  = sm + 2 * 32 * MRS;   // [128][128]
    float* W2s  = W1s + 128 * 128;     // [128][128]

    const int tid = threadIdx.x;
    const int r   = tid >> 4;          // row 0..31
    const int cg  = tid & 15;          // col-group 0..15
    const int c0  = cg * 8;
    const int r0g = blockIdx.x * 32;
    const uint32_t smb = s2u(sm);

    // stage A + Wm1 (group A)
    for (int i = tid; i < 32 * 32; i += 512) {
        int row = i >> 5, c4 = (i & 31) * 4;
        cpasync16(smb + (uint32_t)(row * MRS + c4) * 4,
                  in + (r0g + row) * 128 + c4);
    }
    for (int i = tid; i < 128 * 32; i += 512) {
        int row = i >> 5, c4 = (i & 31) * 4;
        cpasync16(smb + (uint32_t)(2 * 32 * MRS + row * 128 + c4) * 4,
                  Wm1 + row * 128 + c4);
    }
    CP_COMMIT();
    for (int i = tid; i < 128 * 32; i += 512) {   // Wm2 (group B)
        int row = i >> 5, c4 = (i & 31) * 4;
        cpasync16(smb + (uint32_t)(2 * 32 * MRS + 128 * 128 + row * 128 + c4) * 4,
                  Wm2 + row * 128 + c4);
    }
    CP_COMMIT();

    CP_WAIT1();          // A + Wm1 ready
    __syncthreads();

    // layer 1
    unsigned long long acc[4];
#pragma unroll
    for (int c = 0; c < 4; ++c) acc[c] = 0ull;
    {
        const float* Ar = A + r * MRS;
#pragma unroll 8
        for (int k = 0; k < 128; ++k) {
            unsigned long long ad = dup2(Ar[k]);
            ulonglong2 w0 = *(const ulonglong2*)&W1s[k * 128 + c0];
            ulonglong2 w1 = *(const ulonglong2*)&W1s[k * 128 + c0 + 4];
            fma2(acc[0], ad, w0.x); fma2(acc[1], ad, w0.y);
            fma2(acc[2], ad, w1.x); fma2(acc[3], ad, w1.y);
        }
        float* Mr = Mid + r * MRS + c0;
#pragma unroll
        for (int c = 0; c < 8; ++c) {
            unsigned long long v = acc[c >> 1];
            float y = ((c & 1) ? hi32(v) : lo32(v)) + bm1[c0 + c];
            Mr[c] = gelu_f(y);
        }
    }
    CP_WAIT0();          // Wm2 ready
    __syncthreads();

    // layer 2
#pragma unroll
    for (int c = 0; c < 4; ++c) acc[c] = 0ull;
    {
        const float* Mr = Mid + r * MRS;
#pragma unroll 8
        for (int k = 0; k < 128; ++k) {
            unsigned long long ad = dup2(Mr[k]);
            ulonglong2 w0 = *(const ulonglong2*)&W2s[k * 128 + c0];
            ulonglong2 w1 = *(const ulonglong2*)&W2s[k * 128 + c0 + 4];
            fma2(acc[0], ad, w0.x); fma2(acc[1], ad, w0.y);
            fma2(acc[2], ad, w1.x); fma2(acc[3], ad, w1.y);
        }
        float o[8];
#pragma unroll
        for (int c = 0; c < 8; ++c) {
            unsigned long long v = acc[c >> 1];
            o[c] = ((c & 1) ? hi32(v) : lo32(v)) + bm2[c0 + c];
        }
        float* og = out + (r0g + r) * 128 + c0;
        *(float4*)&og[0] = make_float4(o[0], o[1], o[2], o[3]);
        *(float4*)&og[4] = make_float4(o[4], o[5], o[6], o[7]);
    }
}

// ---------------------------------------------------------------------------
__global__ void copy_kernel(const float4* __restrict__ src,
                            float4* __restrict__ dst, int n4)
{
    int i = blockIdx.x * blockDim.x + threadIdx.x;
    if (i < n4) dst[i] = src[i];
}

// ---------------------------------------------------------------------------
extern "C" void kernel_launch(void* const* d_in, const int* in_sizes, int n_in,
                              void* d_out, int out_size)
{
    const float* trend0 = (const float*)d_in[0];
    const float* trend1 = (const float*)d_in[1];
    const float* trend2 = (const float*)d_in[2];
    const float* W1     = (const float*)d_in[3];
    const float* b1     = (const float*)d_in[4];
    const float* W2     = (const float*)d_in[5];
    const float* b2     = (const float*)d_in[6];
    const float* Wm1    = (const float*)d_in[7];
    const float* bm1    = (const float*)d_in[8];
    const float* Wm2    = (const float*)d_in[9];
    const float* bm2    = (const float*)d_in[10];

    float* out = (float*)d_out;
    float* O0 = out;             // mlp(trend0 + res1)
    float* O1 = out + BSH;       // mlp(trend1 + res0)
    float* O2 = out + 2 * BSH;   // trend2

    float* pM;
    cudaGetSymbolAddress((void**)&pM, g_M);

    cudaFuncSetAttribute(mlp_fused, cudaFuncAttributeMaxDynamicSharedMemorySize,
                         MLP_SMEM_BYTES);

    dim3 blk(256);
    dim3 mixGrid(72 * Bc);       // 2304 blocks, descending class size
    dim3 initGrid(BSH / 4 / 256);

    // scale i=0: X = trend2, base = trend1 -> O1 = mlp(M0)
    init_kernel<<<initGrid, blk>>>((const float4*)trend1, b2, (float4*)pM);
    mix_kernel<<<mixGrid, blk>>>(trend2, W1, b1, W2, pM);
    mlp_fused<<<128, 512, MLP_SMEM_BYTES>>>(pM, Wm1, bm1, Wm2, bm2, O1);

    // scale i=1: X = O1, base = trend0 -> O0 = mlp(M1)
    init_kernel<<<initGrid, blk>>>((const float4*)trend0, b2 + Sc, (float4*)pM);
    mix_kernel<<<mixGrid, blk>>>(O1, W1 + Sc * Sc * Sc, b1 + Sc * Sc,
                                 W2 + Sc * Sc, pM);
    mlp_fused<<<128, 512, MLP_SMEM_BYTES>>>(pM, Wm1, bm1, Wm2, bm2, O0);

    // out2 = trend2
    copy_kernel<<<BSH / 4 / 256, 256>>>((const float4*)trend2, (float4*)O2,
                                        BSH / 4);
}